// round 16
// baseline (speedup 1.0000x reference)
#include <cuda_runtime.h>
#include <cuda_bf16.h>
#include <cstdint>
#include <math.h>

#define NRN 10000
#define NCN 5000
#define ERN 160000
#define ECN 80000
#define HD  128
#define NSPLIT 3
#define NCAND (NSPLIT*12)

// ---------------- scratch (device globals; no allocation) ----------------
__device__ float d_hA_r[NRN*HD];
__device__ float d_hB_r[NRN*HD];
__device__ float d_hA_c[NCN*HD];
__device__ float d_hB_c[NCN*HD];
__device__ __nv_bfloat16 d_hrb[NRN*HD];
__device__ __nv_bfloat16 d_hcb[NCN*HD];
__device__ float d_as[NRN+NCN];
__device__ float d_ad[NRN+NCN];
__device__ int   d_cnt_r[NRN];
__device__ int   d_off_r[NRN+1];
__device__ int   d_cur_r[NRN];
__device__ int   d_srcs_r[ERN+NRN];
__device__ int   d_cnt_c[NCN];
__device__ int   d_off_c[NCN+1];
__device__ int   d_cur_c[NCN];
__device__ int   d_srcs_c[ECN+NCN];
__device__ float d_rn[NRN];
__device__ int   d_cand[NCN*NCAND];
__device__ float d_psum[NRN*HD];
__device__ float d_pcnt[NRN];

// ---------------- mma / cp.async helpers (baseline PTX, sm_80+) ----------
__device__ __forceinline__ uint32_t smem_u32(const void* p) {
    uint32_t a;
    asm("{ .reg .u64 t; cvta.to.shared.u64 t, %1; cvt.u32.u64 %0, t; }" : "=r"(a) : "l"(p));
    return a;
}
__device__ __forceinline__ void ldm4(uint32_t* r, uint32_t addr) {
    asm volatile("ldmatrix.sync.aligned.m8n8.x4.shared.b16 {%0,%1,%2,%3}, [%4];"
        : "=r"(r[0]), "=r"(r[1]), "=r"(r[2]), "=r"(r[3]) : "r"(addr));
}
__device__ __forceinline__ void mma16816(float* c, const uint32_t* a, const uint32_t* b) {
    asm volatile("mma.sync.aligned.m16n8k16.row.col.f32.bf16.bf16.f32 "
        "{%0,%1,%2,%3}, {%4,%5,%6,%7}, {%8,%9}, {%0,%1,%2,%3};"
        : "+f"(c[0]), "+f"(c[1]), "+f"(c[2]), "+f"(c[3])
        : "r"(a[0]), "r"(a[1]), "r"(a[2]), "r"(a[3]), "r"(b[0]), "r"(b[1]));
}
__device__ __forceinline__ void cp16(uint32_t dst, const void* src, bool pred) {
    int sz = pred ? 16 : 0;
    asm volatile("cp.async.cg.shared.global [%0], [%1], 16, %2;"
                 :: "r"(dst), "l"(src), "r"(sz));
}
#define CP_COMMIT() asm volatile("cp.async.commit_group;" ::: "memory")
#define CP_WAIT0()  asm volatile("cp.async.wait_group 0;" ::: "memory")

// ---------------- init: all fills in one launch ----------------
__global__ void k_init(int* cnt_r, int* cnt_c, float* psum, float* pcnt,
                       int nr, int nc) {
    int i = blockIdx.x*blockDim.x + threadIdx.x;
    if (i < nr) { cnt_r[i] = 1; pcnt[i] = 0.f; }
    if (i < nc) cnt_c[i] = 1;
    if (i < nr*HD) psum[i] = 0.f;
}

// histogram of in-degree for both graphs
__global__ void k_hist_both(const int* __restrict__ ei_r, int er, int* cnt_r,
                            const int* __restrict__ ei_c, int ec, int* cnt_c) {
    int i = blockIdx.x*blockDim.x + threadIdx.x;
    if (i < er) atomicAdd(&cnt_r[ei_r[er + i]], 1);
    else if (i < er + ec) {
        int j = i - er;
        atomicAdd(&cnt_c[ei_c[ec + j]], 1);
    }
}

// single-block exclusive scan per graph (block 0: resting, block 1: collider)
__global__ void k_scan_both(const int* __restrict__ cnt_r, int* off_r, int* cur_r, int nr,
                            const int* __restrict__ cnt_c, int* off_c, int* cur_c, int nc) {
    const int* cnt = blockIdx.x ? cnt_c : cnt_r;
    int* off = blockIdx.x ? off_c : off_r;
    int* cur = blockIdx.x ? cur_c : cur_r;
    int n   = blockIdx.x ? nc : nr;
    __shared__ int ps[1024];
    int t = threadIdx.x;
    int chunk = (n + 1023) / 1024;
    int beg = t * chunk;
    int end = beg + chunk; if (end > n) end = n;
    int s = 0;
    for (int i = beg; i < end; i++) s += cnt[i];
    ps[t] = s;
    __syncthreads();
    for (int o = 1; o < 1024; o <<= 1) {
        int v = 0;
        if (t >= o) v = ps[t - o];
        __syncthreads();
        ps[t] += v;
        __syncthreads();
    }
    int run = (t == 0) ? 0 : ps[t - 1];
    for (int i = beg; i < end; i++) {
        off[i] = run; cur[i] = run;
        run += cnt[i];
    }
    if (t == 1023) off[n] = ps[1023];
}

// scatter edges + self loops for both graphs
__global__ void k_scatter_both(const int* __restrict__ ei_r, int er, int nr,
                               int* cur_r, int* srcs_r,
                               const int* __restrict__ ei_c, int ec, int nc,
                               int* cur_c, int* srcs_c) {
    int i = blockIdx.x*blockDim.x + threadIdx.x;
    int s, d; int* cur; int* srcs;
    if (i < er)                { s = ei_r[i]; d = ei_r[er + i]; cur = cur_r; srcs = srcs_r; }
    else if (i < er + nr)      { s = i - er; d = s; cur = cur_r; srcs = srcs_r; }
    else if (i < er + nr + ec) { int j = i - er - nr; s = ei_c[j]; d = ei_c[ec + j]; cur = cur_c; srcs = srcs_c; }
    else if (i < er + nr + ec + nc) { s = i - er - nr - ec; d = s; cur = cur_c; srcs = srcs_c; }
    else return;
    int pos = atomicAdd(&cur[d], 1);
    srcs[pos] = s;
}

// ---------------- layer-1 linear (tiny F) + fused attention scores ----------
__global__ void __launch_bounds__(128) k_lin_small_both(
        const float* __restrict__ x_r, const float* __restrict__ W_r,
        const float* __restrict__ avs_r, const float* __restrict__ avd_r,
        const float* __restrict__ x_c, const float* __restrict__ W_c,
        const float* __restrict__ avs_c, const float* __restrict__ avd_c,
        float* __restrict__ h_r, float* __restrict__ h_c,
        float* __restrict__ as_o, float* __restrict__ ad_o, int nr, int nc) {
    int node = blockIdx.x;
    int j = threadIdx.x;
    const float *x, *W, *avs, *avd; float* h; int F;
    if (node < nr) { x = x_r + (size_t)node*3; F = 3; W = W_r; avs = avs_r; avd = avd_r;
                     h = h_r + (size_t)node*HD; }
    else { int l = node - nr; x = x_c + (size_t)l*6; F = 6; W = W_c; avs = avs_c; avd = avd_c;
           h = h_c + (size_t)l*HD; }
    float acc = 0.f;
    for (int k = 0; k < F; k++) acc += x[k] * W[k*HD + j];
    h[j] = acc;
    float ps = acc * avs[j];
    float pd = acc * avd[j];
    #pragma unroll
    for (int o = 16; o; o >>= 1) {
        ps += __shfl_xor_sync(0xffffffffu, ps, o);
        pd += __shfl_xor_sync(0xffffffffu, pd, o);
    }
    __shared__ float sr[4][2];
    int wid = j >> 5, lane = j & 31;
    if (lane == 0) { sr[wid][0] = ps; sr[wid][1] = pd; }
    __syncthreads();
    if (j == 0) {
        as_o[node] = sr[0][0]+sr[1][0]+sr[2][0]+sr[3][0];
        ad_o[node] = sr[0][1]+sr[1][1]+sr[2][1]+sr[3][1];
    }
}

// ---------------- layer-2 linear (F=128) + fused attention scores ---------
__global__ void __launch_bounds__(128) k_lin128_both(
        const float* __restrict__ x_r, const float* __restrict__ W_r,
        const float* __restrict__ avs_r, const float* __restrict__ avd_r,
        const float* __restrict__ x_c, const float* __restrict__ W_c,
        const float* __restrict__ avs_c, const float* __restrict__ avd_c,
        float* __restrict__ h_r, float* __restrict__ h_c,
        float* __restrict__ as_o, float* __restrict__ ad_o,
        int nr, int nc, int nb_r) {
    __shared__ float sx[16][HD];
    __shared__ float sred[4][16][2];
    int j = threadIdx.x;
    int wid = j >> 5, lane = j & 31;
    const float *x, *W, *avs, *avd; float* h; int n, nb, sbase;
    if ((int)blockIdx.x < nb_r) { x = x_r; W = W_r; avs = avs_r; avd = avd_r; h = h_r;
                                  n = nr; nb = blockIdx.x*16; sbase = 0; }
    else { x = x_c; W = W_c; avs = avs_c; avd = avd_c; h = h_c;
           n = nc; nb = (blockIdx.x - nb_r)*16; sbase = nr; }
    #pragma unroll
    for (int i = 0; i < 16; i++) {
        int node = nb + i;
        sx[i][j] = (node < n) ? x[(size_t)node*HD + j] : 0.f;
    }
    __syncthreads();
    float avsj = avs[j], avdj = avd[j];
    for (int i = 0; i < 16; i += 4) {
        float a0 = 0.f, a1 = 0.f, a2 = 0.f, a3 = 0.f;
        #pragma unroll 4
        for (int k = 0; k < HD; k++) {
            float w = W[k*HD + j];
            a0 += sx[i+0][k] * w;
            a1 += sx[i+1][k] * w;
            a2 += sx[i+2][k] * w;
            a3 += sx[i+3][k] * w;
        }
        if (nb+i+0 < n) h[(size_t)(nb+i+0)*HD + j] = a0;
        if (nb+i+1 < n) h[(size_t)(nb+i+1)*HD + j] = a1;
        if (nb+i+2 < n) h[(size_t)(nb+i+2)*HD + j] = a2;
        if (nb+i+3 < n) h[(size_t)(nb+i+3)*HD + j] = a3;
        float r0s = a0*avsj, r1s = a1*avsj, r2s = a2*avsj, r3s = a3*avsj;
        float r0d = a0*avdj, r1d = a1*avdj, r2d = a2*avdj, r3d = a3*avdj;
        #pragma unroll
        for (int o = 16; o; o >>= 1) {
            r0s += __shfl_xor_sync(0xffffffffu, r0s, o);
            r1s += __shfl_xor_sync(0xffffffffu, r1s, o);
            r2s += __shfl_xor_sync(0xffffffffu, r2s, o);
            r3s += __shfl_xor_sync(0xffffffffu, r3s, o);
            r0d += __shfl_xor_sync(0xffffffffu, r0d, o);
            r1d += __shfl_xor_sync(0xffffffffu, r1d, o);
            r2d += __shfl_xor_sync(0xffffffffu, r2d, o);
            r3d += __shfl_xor_sync(0xffffffffu, r3d, o);
        }
        if (lane == 0) {
            sred[wid][i+0][0] = r0s; sred[wid][i+0][1] = r0d;
            sred[wid][i+1][0] = r1s; sred[wid][i+1][1] = r1d;
            sred[wid][i+2][0] = r2s; sred[wid][i+2][1] = r2d;
            sred[wid][i+3][0] = r3s; sred[wid][i+3][1] = r3d;
        }
    }
    __syncthreads();
    if (j < 32) {
        int node = j >> 1, sel = j & 1;
        if (nb + node < n) {
            float v = sred[0][node][sel]+sred[1][node][sel]
                     +sred[2][node][sel]+sred[3][node][sel];
            if (sel == 0) as_o[sbase + nb + node] = v;
            else          ad_o[sbase + nb + node] = v;
        }
    }
}

// ---------------- GAT softmax-aggregate (both branches) -------------------
// warp per node; lane owns feature cols [4*lane, 4*lane+4) -> LDG.128 gather
__global__ void __launch_bounds__(128) k_agg_both(
        const float* __restrict__ h_r, const float* __restrict__ h_c,
        const float* __restrict__ as, const float* __restrict__ ad,
        const int* __restrict__ off_r, const int* __restrict__ srcs_r,
        const int* __restrict__ off_c, const int* __restrict__ srcs_c,
        const float* __restrict__ bias_r, const float* __restrict__ bias_c,
        float* __restrict__ out_r, float* __restrict__ out_c,
        __nv_bfloat16* hrb, __nv_bfloat16* hcb, float* rn,
        int nr, int nc, int epi) {
    __shared__ float swg[4][128];
    __shared__ int   ssi[4][128];
    int w = (blockIdx.x*blockDim.x + threadIdx.x) >> 5;
    int wl = threadIdx.x >> 5;
    int lane = threadIdx.x & 31;
    if (w >= nr + nc) return;
    const float *h, *bias; const int *off, *srcs; float* out;
    int local, sbase;
    if (w < nr) { h = h_r; bias = bias_r; off = off_r; srcs = srcs_r; out = out_r;
                  local = w; sbase = 0; }
    else { h = h_c; bias = bias_c; off = off_c; srcs = srcs_c; out = out_c;
           local = w - nr; sbase = nr; }
    int beg = off[local], end = off[local+1];
    int E = end - beg;
    float adn = ad[sbase + local];
    float a0 = 0.f, a1 = 0.f, a2 = 0.f, a3 = 0.f;
    float inv;
    const float4* h4 = (const float4*)h;
    if (E <= 128) {
        float m = -3.4e38f;
        for (int base = 0; base < E; base += 32) {
            int i = base + lane;
            float e = -3.4e38f;
            if (i < E) {
                int s = srcs[beg + i];
                ssi[wl][i] = s;
                e = as[sbase + s] + adn;
                e = (e > 0.f) ? e : 0.2f*e;
                swg[wl][i] = e;
            }
            m = fmaxf(m, e);
        }
        #pragma unroll
        for (int o = 16; o; o >>= 1) m = fmaxf(m, __shfl_xor_sync(0xffffffffu, m, o));
        float dsum = 0.f;
        for (int base = 0; base < E; base += 32) {
            int i = base + lane;
            if (i < E) {
                float wv = __expf(swg[wl][i] - m);
                swg[wl][i] = wv;
                dsum += wv;
            }
        }
        #pragma unroll
        for (int o = 16; o; o >>= 1) dsum += __shfl_xor_sync(0xffffffffu, dsum, o);
        inv = 1.f / dsum;
        __syncwarp();
        #pragma unroll 4
        for (int e = 0; e < E; e++) {
            int s = ssi[wl][e];
            float al = swg[wl][e];
            float4 hv = h4[(size_t)s*32 + lane];
            a0 += al * hv.x;
            a1 += al * hv.y;
            a2 += al * hv.z;
            a3 += al * hv.w;
        }
    } else {
        float m = -3.4e38f;
        for (int i = beg + lane; i < end; i += 32) {
            float e = as[sbase + srcs[i]] + adn;
            e = (e > 0.f) ? e : 0.2f*e;
            m = fmaxf(m, e);
        }
        #pragma unroll
        for (int o = 16; o; o >>= 1) m = fmaxf(m, __shfl_xor_sync(0xffffffffu, m, o));
        float denom = 0.f;
        for (int i = beg; i < end; i++) {
            int s = srcs[i];
            float e = as[sbase + s] + adn;
            e = (e > 0.f) ? e : 0.2f*e;
            float wgt = __expf(e - m);
            denom += wgt;
            float4 hv = h4[(size_t)s*32 + lane];
            a0 += wgt * hv.x;
            a1 += wgt * hv.y;
            a2 += wgt * hv.z;
            a3 += wgt * hv.w;
        }
        inv = 1.f / denom;
    }
    float4 bv = ((const float4*)bias)[lane];
    float v0 = fmaxf(a0*inv + bv.x, 0.f);
    float v1 = fmaxf(a1*inv + bv.y, 0.f);
    float v2 = fmaxf(a2*inv + bv.z, 0.f);
    float v3 = fmaxf(a3*inv + bv.w, 0.f);
    float4* op = (float4*)(out + (size_t)local*HD) + lane;
    *op = make_float4(v0, v1, v2, v3);
    if (epi) {
        __nv_bfloat16* hb = (w < nr) ? hrb : hcb;
        __nv_bfloat162 p01(__float2bfloat16(v0), __float2bfloat16(v1));
        __nv_bfloat162 p23(__float2bfloat16(v2), __float2bfloat16(v3));
        uint2 pk = make_uint2(*(uint32_t*)&p01, *(uint32_t*)&p23);
        *((uint2*)(hb + (size_t)local*HD) + lane) = pk;
        if (w < nr) {
            float sq = v0*v0 + v1*v1 + v2*v2 + v3*v3;
            #pragma unroll
            for (int o = 16; o; o >>= 1) sq += __shfl_xor_sync(0xffffffffu, sq, o);
            if (lane == 0) rn[local] = sq;
        }
    }
}

// ---------------- bf16 HMMA kNN candidate pass (cp.async pipelined) --------
// 512 threads / 16 warps; warp = (m-tile, n-quarter); NSPLIT=3 -> 120 CTAs.
// Epilogue merges the 4 lane sub-buckets of each (row, quarter) bucket via
// shuffles -> top-3 per (row, quarter, split). NCAND = 3*4*3 = 36.
#define TPAD 136                         // bf16 elements per smem row (272 B)
#define SMB_A   0
#define SMB_B0  (128*TPAD*2)             // 34816
#define SMB_B1  (SMB_B0 + 128*TPAD*2)    // 69632
#define SMB_RN0 (SMB_B1 + 128*TPAD*2)    // 104448
#define SMB_RN1 (SMB_RN0 + 512)          // 104960
#define KNN_SMEM_BYTES (SMB_RN1 + 512)   // 105472
#define KNN_THREADS 512

__device__ __forceinline__ void knn_prefetch(uint32_t sB, uint32_t sRN,
        const __nv_bfloat16* __restrict__ hr, const float* __restrict__ rn,
        int rb, int r_end, int t) {
    #pragma unroll
    for (int i = 0; i < 4; i++) {
        int idx = t + i*KNN_THREADS;
        int row = idx >> 4, seg = idx & 15;
        uint32_t dst = sB + row*(TPAD*2) + seg*16;
        const char* src = (const char*)(hr + (size_t)(rb+row)*HD) + seg*16;
        cp16(dst, src, rb + row < r_end);
    }
    if (t < 32) {
        uint32_t dst = sRN + t*16;
        const char* src = (const char*)(rn + rb) + t*16;
        cp16(dst, src, rb + t*4 < r_end);
    }
}

__global__ void __launch_bounds__(KNN_THREADS, 1) k_knn_mma(
        const __nv_bfloat16* __restrict__ hc,
        const __nv_bfloat16* __restrict__ hr,
        const float* __restrict__ rn,
        int* __restrict__ cand, int nc, int nr) {
    extern __shared__ __align__(16) char dsm[];
    uint32_t sbase = smem_u32(dsm);
    uint32_t sA = sbase + SMB_A;
    __nv_bfloat16* sAp = (__nv_bfloat16*)(dsm + SMB_A);

    int t = threadIdx.x;
    int wid = t >> 5, lane = t & 31;
    int m0 = (wid & 3) * 32;             // warp's collider rows
    int nq = wid >> 2;                   // warp's 32-col resting quarter (0-3)
    int n0 = nq * 32;
    int cb = blockIdx.x * 128;
    int slen = (((nr + NSPLIT - 1) / NSPLIT) + 127) & ~127;
    int r_beg = blockIdx.y * slen;
    int r_end = r_beg + slen; if (r_end > nr) r_end = nr;
    int nchunks = (r_end > r_beg) ? ((r_end - r_beg + 127) >> 7) : 0;

    if (nchunks > 0) {
        knn_prefetch(sbase + SMB_B0, sbase + SMB_RN0, hr, rn, r_beg, r_end, t);
        CP_COMMIT();
    }

    const uint32_t* hc2 = (const uint32_t*)hc;
    for (int idx = t; idx < 128*64; idx += KNN_THREADS) {
        int row = idx >> 6, cp = idx & 63;
        int c = cb + row;
        uint32_t v = (c < nc) ? hc2[(size_t)c*64 + cp] : 0u;
        *(uint32_t*)(sAp + row*TPAD + cp*2) = v;
    }

    const float FINF = __int_as_float(0x7f800000);
    float bd[4][3]; int bi[4][3];
    #pragma unroll
    for (int b = 0; b < 4; b++)
        #pragma unroll
        for (int q = 0; q < 3; q++) { bd[b][q] = FINF; bi[b][q] = 0x7fffffff; }

    for (int ci = 0; ci < nchunks; ci++) {
        int rb = r_beg + ci*128;
        int buf = ci & 1;
        CP_WAIT0();
        __syncthreads();
        if (ci + 1 < nchunks) {
            uint32_t nb_ = buf ? SMB_B0 : SMB_B1;
            uint32_t nrr = buf ? SMB_RN0 : SMB_RN1;
            knn_prefetch(sbase + nb_, sbase + nrr, hr, rn, rb + 128, r_end, t);
            CP_COMMIT();
        }
        uint32_t sB = sbase + (buf ? SMB_B1 : SMB_B0);
        const float* srnp = (const float*)(dsm + (buf ? SMB_RN1 : SMB_RN0));

        float acc[2][4][4];
        #pragma unroll
        for (int mt = 0; mt < 2; mt++)
            #pragma unroll
            for (int nt = 0; nt < 4; nt++)
                #pragma unroll
                for (int q = 0; q < 4; q++) acc[mt][nt][q] = 0.f;

        #pragma unroll
        for (int kk = 0; kk < 8; kk++) {
            int k0 = kk * 16;
            uint32_t afr[2][4];
            #pragma unroll
            for (int mt = 0; mt < 2; mt++) {
                uint32_t addr = sA + ((m0 + mt*16 + (lane & 15))*TPAD
                                      + k0 + (lane >> 4)*8) * 2;
                ldm4(afr[mt], addr);
            }
            #pragma unroll
            for (int nt4 = 0; nt4 < 2; nt4++) {
                uint32_t bfr[4];
                uint32_t addr = sB + ((n0 + nt4*16 + (lane & 7) + ((lane >> 4) & 1)*8)*TPAD
                                      + k0 + ((lane >> 3) & 1)*8) * 2;
                ldm4(bfr, addr);
                #pragma unroll
                for (int mt = 0; mt < 2; mt++) {
                    mma16816(acc[mt][2*nt4],   afr[mt], bfr);
                    mma16816(acc[mt][2*nt4+1], afr[mt], bfr + 2);
                }
            }
        }

        bool full = (rb + 128 <= r_end);
        if (full) {
            #pragma unroll
            for (int mt = 0; mt < 2; mt++) {
                #pragma unroll
                for (int half = 0; half < 2; half++) {
                    int b = mt*2 + half;
                    #pragma unroll
                    for (int nt = 0; nt < 4; nt++) {
                        #pragma unroll
                        for (int q = 0; q < 2; q++) {
                            int col = n0 + nt*8 + (lane & 3)*2 + q;
                            float s = srnp[col] - 2.f * acc[mt][nt][half*2 + q];
                            if (s < bd[b][2]) {
                                bd[b][2] = s; bi[b][2] = rb + col;
                                #pragma unroll
                                for (int z = 2; z > 0; z--) {
                                    if (bd[b][z] < bd[b][z-1]) {
                                        float tf = bd[b][z]; bd[b][z] = bd[b][z-1]; bd[b][z-1] = tf;
                                        int   ti = bi[b][z]; bi[b][z] = bi[b][z-1]; bi[b][z-1] = ti;
                                    }
                                }
                            }
                        }
                    }
                }
            }
        } else {
            #pragma unroll
            for (int mt = 0; mt < 2; mt++) {
                #pragma unroll
                for (int half = 0; half < 2; half++) {
                    int b = mt*2 + half;
                    #pragma unroll
                    for (int nt = 0; nt < 4; nt++) {
                        #pragma unroll
                        for (int q = 0; q < 2; q++) {
                            int col = n0 + nt*8 + (lane & 3)*2 + q;
                            int rcol = rb + col;
                            float s = srnp[col] - 2.f * acc[mt][nt][half*2 + q];
                            if (rcol < r_end && s < bd[b][2]) {
                                bd[b][2] = s; bi[b][2] = rcol;
                                #pragma unroll
                                for (int z = 2; z > 0; z--) {
                                    if (bd[b][z] < bd[b][z-1]) {
                                        float tf = bd[b][z]; bd[b][z] = bd[b][z-1]; bd[b][z-1] = tf;
                                        int   ti = bi[b][z]; bi[b][z] = bi[b][z-1]; bi[b][z-1] = ti;
                                    }
                                }
                            }
                        }
                    }
                }
            }
        }
        __syncthreads();
    }

    // merge 4 lane sub-buckets of each (row, quarter) bucket -> lane&3 == 0
    #pragma unroll
    for (int b = 0; b < 4; b++) {
        #pragma unroll
        for (int j = 1; j < 4; j++) {
            #pragma unroll
            for (int q = 0; q < 3; q++) {
                float od = __shfl_sync(0xffffffffu, bd[b][q], (lane & ~3) + j);
                int   oi = __shfl_sync(0xffffffffu, bi[b][q], (lane & ~3) + j);
                if ((lane & 3) == 0 && od < bd[b][2]) {
                    bd[b][2] = od; bi[b][2] = oi;
                    #pragma unroll
                    for (int z = 2; z > 0; z--) {
                        if (bd[b][z] < bd[b][z-1]) {
                            float tf = bd[b][z]; bd[b][z] = bd[b][z-1]; bd[b][z-1] = tf;
                            int   ti = bi[b][z]; bi[b][z] = bi[b][z-1]; bi[b][z-1] = ti;
                        }
                    }
                }
            }
        }
        if ((lane & 3) == 0) {
            int row = m0 + (b >> 1)*16 + (b & 1)*8 + (lane >> 2);
            int c = cb + row;
            if (c < nc) {
                int* cp = cand + (size_t)c*NCAND + blockIdx.y*12 + nq*3;
                cp[0] = bi[b][0];
                cp[1] = bi[b][1];
                cp[2] = bi[b][2];
            }
        }
    }
}

// exact fp32 rescore -> top-3, fused scatter-mean pool
__global__ void k_rescore_pool(const float* __restrict__ hc, const float* __restrict__ hr,
                               const float* __restrict__ rn, const int* __restrict__ cand,
                               float* psum, float* pcnt, int nc, int nr) {
    int w = (blockIdx.x*blockDim.x + threadIdx.x) >> 5;
    int lane = threadIdx.x & 31;
    if (w >= nc) return;
    const float4* cq = (const float4*)(hc + (size_t)w*HD);
    float4 q = cq[lane];
    float t0 = 3.4e38f, t1 = 3.4e38f, t2 = 3.4e38f;
    int   i0 = 0x7fffffff, i1 = 0x7fffffff, i2 = 0x7fffffff;
    const int* cp = cand + (size_t)w * NCAND;
    for (int qi = 0; qi < NCAND; qi++) {
        int i = cp[qi];
        if ((unsigned)i >= (unsigned)nr) continue;
        const float4 r4 = ((const float4*)(hr + (size_t)i*HD))[lane];
        float dot = q.x*r4.x + q.y*r4.y + q.z*r4.z + q.w*r4.w;
        #pragma unroll
        for (int o = 16; o; o >>= 1) dot += __shfl_xor_sync(0xffffffffu, dot, o);
        float dv = rn[i] - 2.f * dot;
        if (i == i0 || i == i1 || i == i2) continue;
        if (dv < t2 || (dv == t2 && i < i2)) {
            if (dv < t0 || (dv == t0 && i < i0)) {
                t2=t1; i2=i1; t1=t0; i1=i0; t0=dv; i0=i;
            } else if (dv < t1 || (dv == t1 && i < i1)) {
                t2=t1; i2=i1; t1=dv; i1=i;
            } else {
                t2=dv; i2=i;
            }
        }
    }
    int nb[3] = { i0, i1, i2 };
    #pragma unroll
    for (int z = 0; z < 3; z++) {
        int r = nb[z];
        if ((unsigned)r >= (unsigned)nr) continue;   // sentinel safety
        float* pp = psum + (size_t)r*HD + lane*4;
        atomicAdd(pp + 0, q.x);
        atomicAdd(pp + 1, q.y);
        atomicAdd(pp + 2, q.z);
        atomicAdd(pp + 3, q.w);
        if (lane == 0) atomicAdd(&pcnt[r], 1.f);
    }
}

__global__ void k_decode(const float* __restrict__ hr, const float* __restrict__ psum,
                         const float* __restrict__ pcnt,
                         const float* __restrict__ Wd, const float* __restrict__ bd,
                         float* __restrict__ out, int n) {
    int w = (blockIdx.x*blockDim.x + threadIdx.x) >> 5;
    int lane = threadIdx.x & 31;
    if (w >= n) return;
    float inv = 1.f / fmaxf(pcnt[w], 1.f);
    float4 hv = ((const float4*)(hr + (size_t)w*HD))[lane];
    float4 pv = ((const float4*)(psum + (size_t)w*HD))[lane];
    float a0 = 0.f, a1 = 0.f, a2 = 0.f;
    #pragma unroll
    for (int k = 0; k < 4; k++) {
        int j = lane*4 + k;
        float v = (k == 0) ? hv.x : (k == 1) ? hv.y : (k == 2) ? hv.z : hv.w;
        float p = ((k == 0) ? pv.x : (k == 1) ? pv.y : (k == 2) ? pv.z : pv.w) * inv;
        a0 += v*Wd[j*3 + 0] + p*Wd[(HD + j)*3 + 0];
        a1 += v*Wd[j*3 + 1] + p*Wd[(HD + j)*3 + 1];
        a2 += v*Wd[j*3 + 2] + p*Wd[(HD + j)*3 + 2];
    }
    #pragma unroll
    for (int o = 16; o; o >>= 1) {
        a0 += __shfl_xor_sync(0xffffffffu, a0, o);
        a1 += __shfl_xor_sync(0xffffffffu, a1, o);
        a2 += __shfl_xor_sync(0xffffffffu, a2, o);
    }
    if (lane == 0) {
        out[w*3 + 0] = a0 + bd[0];
        out[w*3 + 1] = a1 + bd[1];
        out[w*3 + 2] = a2 + bd[2];
    }
}

// ---------------- host ----------------
static inline int cdiv(int a, int b) { return (a + b - 1) / b; }

extern "C" void kernel_launch(void* const* d_in, const int* in_sizes, int n_in,
                              void* d_out, int out_size) {
    const float* x_r  = (const float*)d_in[0];
    const int*   ei_r = (const int*)  d_in[1];
    const float* x_c  = (const float*)d_in[2];
    const int*   ei_c = (const int*)  d_in[3];
    const float* W1r  = (const float*)d_in[4];
    const float* as1r = (const float*)d_in[5];
    const float* ad1r = (const float*)d_in[6];
    const float* b1r  = (const float*)d_in[7];
    const float* W2r  = (const float*)d_in[8];
    const float* as2r = (const float*)d_in[9];
    const float* ad2r = (const float*)d_in[10];
    const float* b2r  = (const float*)d_in[11];
    const float* W1c  = (const float*)d_in[12];
    const float* as1c = (const float*)d_in[13];
    const float* ad1c = (const float*)d_in[14];
    const float* b1c  = (const float*)d_in[15];
    const float* W2c  = (const float*)d_in[16];
    const float* as2c = (const float*)d_in[17];
    const float* ad2c = (const float*)d_in[18];
    const float* b2c  = (const float*)d_in[19];
    const float* Wd   = (const float*)d_in[20];
    const float* bd   = (const float*)d_in[21];
    float* out = (float*)d_out;

    int nr = in_sizes[0] / 3;
    int er = in_sizes[1] / 2;
    int nc = in_sizes[2] / 6;
    int ec = in_sizes[3] / 2;

    float *hA_r, *hB_r, *hA_c, *hB_c, *as_p, *ad_p, *rn, *psum, *pcnt;
    __nv_bfloat16 *hrb, *hcb;
    int *cnt_r, *off_r, *cur_r, *srcs_r, *cnt_c, *off_c, *cur_c, *srcs_c, *cand;
    cudaGetSymbolAddress((void**)&hA_r,  d_hA_r);
    cudaGetSymbolAddress((void**)&hB_r,  d_hB_r);
    cudaGetSymbolAddress((void**)&hA_c,  d_hA_c);
    cudaGetSymbolAddress((void**)&hB_c,  d_hB_c);
    cudaGetSymbolAddress((void**)&hrb,   d_hrb);
    cudaGetSymbolAddress((void**)&hcb,   d_hcb);
    cudaGetSymbolAddress((void**)&as_p,  d_as);
    cudaGetSymbolAddress((void**)&ad_p,  d_ad);
    cudaGetSymbolAddress((void**)&cnt_r, d_cnt_r);
    cudaGetSymbolAddress((void**)&off_r, d_off_r);
    cudaGetSymbolAddress((void**)&cur_r, d_cur_r);
    cudaGetSymbolAddress((void**)&srcs_r,d_srcs_r);
    cudaGetSymbolAddress((void**)&cnt_c, d_cnt_c);
    cudaGetSymbolAddress((void**)&off_c, d_off_c);
    cudaGetSymbolAddress((void**)&cur_c, d_cur_c);
    cudaGetSymbolAddress((void**)&srcs_c,d_srcs_c);
    cudaGetSymbolAddress((void**)&rn,    d_rn);
    cudaGetSymbolAddress((void**)&cand,  d_cand);
    cudaGetSymbolAddress((void**)&psum,  d_psum);
    cudaGetSymbolAddress((void**)&pcnt,  d_pcnt);

    cudaFuncSetAttribute(k_knn_mma, cudaFuncAttributeMaxDynamicSharedMemorySize,
                         KNN_SMEM_BYTES);

    // 1. fills
    k_init<<<cdiv(nr*HD,256),256>>>(cnt_r, cnt_c, psum, pcnt, nr, nc);
    // 2-3. CSR histogram + scan
    k_hist_both<<<cdiv(er+ec,256),256>>>(ei_r, er, cnt_r, ei_c, ec, cnt_c);
    k_scan_both<<<2,1024>>>(cnt_r, off_r, cur_r, nr, cnt_c, off_c, cur_c, nc);
    // 4. CSR scatter (clock canary in ncu slot)
    k_scatter_both<<<cdiv(er+nr+ec+nc,256),256>>>(ei_r, er, nr, cur_r, srcs_r,
                                                  ei_c, ec, nc, cur_c, srcs_c);
    // 5. layer-1 linear + scores (both)
    k_lin_small_both<<<nr+nc,128>>>(x_r, W1r, as1r, ad1r, x_c, W1c, as1c, ad1c,
                                    hA_r, hA_c, as_p, ad_p, nr, nc);
    // 6. layer-1 aggregate (both)
    k_agg_both<<<cdiv((nr+nc)*32,128),128>>>(hA_r, hA_c, as_p, ad_p,
                                             off_r, srcs_r, off_c, srcs_c,
                                             b1r, b1c, hB_r, hB_c,
                                             (__nv_bfloat16*)0, (__nv_bfloat16*)0,
                                             (float*)0, nr, nc, 0);
    // 7. layer-2 linear + scores (both)
    {
        int nb_r = cdiv(nr,16);
        int nb_c = cdiv(nc,16);
        k_lin128_both<<<nb_r+nb_c,128>>>(hB_r, W2r, as2r, ad2r, hB_c, W2c, as2c, ad2c,
                                         hA_r, hA_c, as_p, ad_p, nr, nc, nb_r);
    }
    // 8. layer-2 aggregate + bf16 convert + rnorm (both)
    k_agg_both<<<cdiv((nr+nc)*32,128),128>>>(hA_r, hA_c, as_p, ad_p,
                                             off_r, srcs_r, off_c, srcs_c,
                                             b2r, b2c, hB_r, hB_c,
                                             hrb, hcb, rn, nr, nc, 1);
    // 9. kNN candidates (bf16 HMMA, 512 threads, warp-merged buckets)
    {
        dim3 g(cdiv(nc,128), NSPLIT);
        k_knn_mma<<<g, KNN_THREADS, KNN_SMEM_BYTES>>>(hcb, hrb, rn, cand, nc, nr);
    }
    // 10. exact rescore (36 candidates) + pool
    k_rescore_pool<<<cdiv(nc*32,256),256>>>(hB_c, hB_r, rn, cand, psum, pcnt, nc, nr);
    // 11. decode
    k_decode<<<cdiv(nr*32,256),256>>>(hB_r, psum, pcnt, Wd, bd, out, nr);
}

// round 17
// speedup vs baseline: 1.4596x; 1.4596x over previous
#include <cuda_runtime.h>
#include <cuda_bf16.h>
#include <cstdint>
#include <math.h>

#define NRN 10000
#define NCN 5000
#define ERN 160000
#define ECN 80000
#define HD  128
#define NSPLIT 3
#define NCAND (NSPLIT*12)

// ---------------- scratch (device globals; no allocation) ----------------
__device__ float d_hA_r[NRN*HD];
__device__ float d_hB_r[NRN*HD];
__device__ float d_hA_c[NCN*HD];
__device__ float d_hB_c[NCN*HD];
__device__ __nv_bfloat16 d_hrb[NRN*HD];
__device__ __nv_bfloat16 d_hcb[NCN*HD];
__device__ float d_as[NRN+NCN];
__device__ float d_ad[NRN+NCN];
__device__ int   d_cnt_r[NRN];
__device__ int   d_off_r[NRN+1];
__device__ int   d_cur_r[NRN];
__device__ int   d_srcs_r[ERN+NRN];
__device__ int   d_cnt_c[NCN];
__device__ int   d_off_c[NCN+1];
__device__ int   d_cur_c[NCN];
__device__ int   d_srcs_c[ECN+NCN];
__device__ float d_rn[NRN];
__device__ int   d_cand[NCN*NCAND];
__device__ float d_psum[NRN*HD];
__device__ float d_pcnt[NRN];

// ---------------- mma / cp.async helpers (baseline PTX, sm_80+) ----------
__device__ __forceinline__ uint32_t smem_u32(const void* p) {
    uint32_t a;
    asm("{ .reg .u64 t; cvta.to.shared.u64 t, %1; cvt.u32.u64 %0, t; }" : "=r"(a) : "l"(p));
    return a;
}
__device__ __forceinline__ void ldm4(uint32_t* r, uint32_t addr) {
    asm volatile("ldmatrix.sync.aligned.m8n8.x4.shared.b16 {%0,%1,%2,%3}, [%4];"
        : "=r"(r[0]), "=r"(r[1]), "=r"(r[2]), "=r"(r[3]) : "r"(addr));
}
__device__ __forceinline__ void mma16816(float* c, const uint32_t* a, const uint32_t* b) {
    asm volatile("mma.sync.aligned.m16n8k16.row.col.f32.bf16.bf16.f32 "
        "{%0,%1,%2,%3}, {%4,%5,%6,%7}, {%8,%9}, {%0,%1,%2,%3};"
        : "+f"(c[0]), "+f"(c[1]), "+f"(c[2]), "+f"(c[3])
        : "r"(a[0]), "r"(a[1]), "r"(a[2]), "r"(a[3]), "r"(b[0]), "r"(b[1]));
}
__device__ __forceinline__ void cp16(uint32_t dst, const void* src, bool pred) {
    int sz = pred ? 16 : 0;
    asm volatile("cp.async.cg.shared.global [%0], [%1], 16, %2;"
                 :: "r"(dst), "l"(src), "r"(sz));
}
#define CP_COMMIT() asm volatile("cp.async.commit_group;" ::: "memory")
#define CP_WAIT0()  asm volatile("cp.async.wait_group 0;" ::: "memory")

// ---------------- init: all fills in one launch ----------------
__global__ void k_init(int* cnt_r, int* cnt_c, float* psum, float* pcnt,
                       int nr, int nc) {
    int i = blockIdx.x*blockDim.x + threadIdx.x;
    if (i < nr) { cnt_r[i] = 1; pcnt[i] = 0.f; }
    if (i < nc) cnt_c[i] = 1;
    if (i < nr*HD) psum[i] = 0.f;
}

// histogram of in-degree for both graphs
__global__ void k_hist_both(const int* __restrict__ ei_r, int er, int* cnt_r,
                            const int* __restrict__ ei_c, int ec, int* cnt_c) {
    int i = blockIdx.x*blockDim.x + threadIdx.x;
    if (i < er) atomicAdd(&cnt_r[ei_r[er + i]], 1);
    else if (i < er + ec) {
        int j = i - er;
        atomicAdd(&cnt_c[ei_c[ec + j]], 1);
    }
}

// single-block exclusive scan per graph (block 0: resting, block 1: collider)
__global__ void k_scan_both(const int* __restrict__ cnt_r, int* off_r, int* cur_r, int nr,
                            const int* __restrict__ cnt_c, int* off_c, int* cur_c, int nc) {
    const int* cnt = blockIdx.x ? cnt_c : cnt_r;
    int* off = blockIdx.x ? off_c : off_r;
    int* cur = blockIdx.x ? cur_c : cur_r;
    int n   = blockIdx.x ? nc : nr;
    __shared__ int ps[1024];
    int t = threadIdx.x;
    int chunk = (n + 1023) / 1024;
    int beg = t * chunk;
    int end = beg + chunk; if (end > n) end = n;
    int s = 0;
    for (int i = beg; i < end; i++) s += cnt[i];
    ps[t] = s;
    __syncthreads();
    for (int o = 1; o < 1024; o <<= 1) {
        int v = 0;
        if (t >= o) v = ps[t - o];
        __syncthreads();
        ps[t] += v;
        __syncthreads();
    }
    int run = (t == 0) ? 0 : ps[t - 1];
    for (int i = beg; i < end; i++) {
        off[i] = run; cur[i] = run;
        run += cnt[i];
    }
    if (t == 1023) off[n] = ps[1023];
}

// scatter edges + self loops for both graphs
__global__ void k_scatter_both(const int* __restrict__ ei_r, int er, int nr,
                               int* cur_r, int* srcs_r,
                               const int* __restrict__ ei_c, int ec, int nc,
                               int* cur_c, int* srcs_c) {
    int i = blockIdx.x*blockDim.x + threadIdx.x;
    int s, d; int* cur; int* srcs;
    if (i < er)                { s = ei_r[i]; d = ei_r[er + i]; cur = cur_r; srcs = srcs_r; }
    else if (i < er + nr)      { s = i - er; d = s; cur = cur_r; srcs = srcs_r; }
    else if (i < er + nr + ec) { int j = i - er - nr; s = ei_c[j]; d = ei_c[ec + j]; cur = cur_c; srcs = srcs_c; }
    else if (i < er + nr + ec + nc) { s = i - er - nr - ec; d = s; cur = cur_c; srcs = srcs_c; }
    else return;
    int pos = atomicAdd(&cur[d], 1);
    srcs[pos] = s;
}

// ---------------- layer-1 linear (tiny F) + fused attention scores ----------
__global__ void __launch_bounds__(128) k_lin_small_both(
        const float* __restrict__ x_r, const float* __restrict__ W_r,
        const float* __restrict__ avs_r, const float* __restrict__ avd_r,
        const float* __restrict__ x_c, const float* __restrict__ W_c,
        const float* __restrict__ avs_c, const float* __restrict__ avd_c,
        float* __restrict__ h_r, float* __restrict__ h_c,
        float* __restrict__ as_o, float* __restrict__ ad_o, int nr, int nc) {
    int node = blockIdx.x;
    int j = threadIdx.x;
    const float *x, *W, *avs, *avd; float* h; int F;
    if (node < nr) { x = x_r + (size_t)node*3; F = 3; W = W_r; avs = avs_r; avd = avd_r;
                     h = h_r + (size_t)node*HD; }
    else { int l = node - nr; x = x_c + (size_t)l*6; F = 6; W = W_c; avs = avs_c; avd = avd_c;
           h = h_c + (size_t)l*HD; }
    float acc = 0.f;
    for (int k = 0; k < F; k++) acc += x[k] * W[k*HD + j];
    h[j] = acc;
    float ps = acc * avs[j];
    float pd = acc * avd[j];
    #pragma unroll
    for (int o = 16; o; o >>= 1) {
        ps += __shfl_xor_sync(0xffffffffu, ps, o);
        pd += __shfl_xor_sync(0xffffffffu, pd, o);
    }
    __shared__ float sr[4][2];
    int wid = j >> 5, lane = j & 31;
    if (lane == 0) { sr[wid][0] = ps; sr[wid][1] = pd; }
    __syncthreads();
    if (j == 0) {
        as_o[node] = sr[0][0]+sr[1][0]+sr[2][0]+sr[3][0];
        ad_o[node] = sr[0][1]+sr[1][1]+sr[2][1]+sr[3][1];
    }
}

// ---------------- layer-2 linear (F=128) + fused attention scores ---------
__global__ void __launch_bounds__(128) k_lin128_both(
        const float* __restrict__ x_r, const float* __restrict__ W_r,
        const float* __restrict__ avs_r, const float* __restrict__ avd_r,
        const float* __restrict__ x_c, const float* __restrict__ W_c,
        const float* __restrict__ avs_c, const float* __restrict__ avd_c,
        float* __restrict__ h_r, float* __restrict__ h_c,
        float* __restrict__ as_o, float* __restrict__ ad_o,
        int nr, int nc, int nb_r) {
    __shared__ float sx[16][HD];
    __shared__ float sred[4][16][2];
    int j = threadIdx.x;
    int wid = j >> 5, lane = j & 31;
    const float *x, *W, *avs, *avd; float* h; int n, nb, sbase;
    if ((int)blockIdx.x < nb_r) { x = x_r; W = W_r; avs = avs_r; avd = avd_r; h = h_r;
                                  n = nr; nb = blockIdx.x*16; sbase = 0; }
    else { x = x_c; W = W_c; avs = avs_c; avd = avd_c; h = h_c;
           n = nc; nb = (blockIdx.x - nb_r)*16; sbase = nr; }
    #pragma unroll
    for (int i = 0; i < 16; i++) {
        int node = nb + i;
        sx[i][j] = (node < n) ? x[(size_t)node*HD + j] : 0.f;
    }
    __syncthreads();
    float avsj = avs[j], avdj = avd[j];
    for (int i = 0; i < 16; i += 4) {
        float a0 = 0.f, a1 = 0.f, a2 = 0.f, a3 = 0.f;
        #pragma unroll 4
        for (int k = 0; k < HD; k++) {
            float w = W[k*HD + j];
            a0 += sx[i+0][k] * w;
            a1 += sx[i+1][k] * w;
            a2 += sx[i+2][k] * w;
            a3 += sx[i+3][k] * w;
        }
        if (nb+i+0 < n) h[(size_t)(nb+i+0)*HD + j] = a0;
        if (nb+i+1 < n) h[(size_t)(nb+i+1)*HD + j] = a1;
        if (nb+i+2 < n) h[(size_t)(nb+i+2)*HD + j] = a2;
        if (nb+i+3 < n) h[(size_t)(nb+i+3)*HD + j] = a3;
        float r0s = a0*avsj, r1s = a1*avsj, r2s = a2*avsj, r3s = a3*avsj;
        float r0d = a0*avdj, r1d = a1*avdj, r2d = a2*avdj, r3d = a3*avdj;
        #pragma unroll
        for (int o = 16; o; o >>= 1) {
            r0s += __shfl_xor_sync(0xffffffffu, r0s, o);
            r1s += __shfl_xor_sync(0xffffffffu, r1s, o);
            r2s += __shfl_xor_sync(0xffffffffu, r2s, o);
            r3s += __shfl_xor_sync(0xffffffffu, r3s, o);
            r0d += __shfl_xor_sync(0xffffffffu, r0d, o);
            r1d += __shfl_xor_sync(0xffffffffu, r1d, o);
            r2d += __shfl_xor_sync(0xffffffffu, r2d, o);
            r3d += __shfl_xor_sync(0xffffffffu, r3d, o);
        }
        if (lane == 0) {
            sred[wid][i+0][0] = r0s; sred[wid][i+0][1] = r0d;
            sred[wid][i+1][0] = r1s; sred[wid][i+1][1] = r1d;
            sred[wid][i+2][0] = r2s; sred[wid][i+2][1] = r2d;
            sred[wid][i+3][0] = r3s; sred[wid][i+3][1] = r3d;
        }
    }
    __syncthreads();
    if (j < 32) {
        int node = j >> 1, sel = j & 1;
        if (nb + node < n) {
            float v = sred[0][node][sel]+sred[1][node][sel]
                     +sred[2][node][sel]+sred[3][node][sel];
            if (sel == 0) as_o[sbase + nb + node] = v;
            else          ad_o[sbase + nb + node] = v;
        }
    }
}

// ---------------- GAT softmax-aggregate (both branches) -------------------
__global__ void __launch_bounds__(128) k_agg_both(
        const float* __restrict__ h_r, const float* __restrict__ h_c,
        const float* __restrict__ as, const float* __restrict__ ad,
        const int* __restrict__ off_r, const int* __restrict__ srcs_r,
        const int* __restrict__ off_c, const int* __restrict__ srcs_c,
        const float* __restrict__ bias_r, const float* __restrict__ bias_c,
        float* __restrict__ out_r, float* __restrict__ out_c,
        __nv_bfloat16* hrb, __nv_bfloat16* hcb, float* rn,
        int nr, int nc, int epi) {
    __shared__ float swg[4][128];
    __shared__ int   ssi[4][128];
    int w = (blockIdx.x*blockDim.x + threadIdx.x) >> 5;
    int wl = threadIdx.x >> 5;
    int lane = threadIdx.x & 31;
    if (w >= nr + nc) return;
    const float *h, *bias; const int *off, *srcs; float* out;
    int local, sbase;
    if (w < nr) { h = h_r; bias = bias_r; off = off_r; srcs = srcs_r; out = out_r;
                  local = w; sbase = 0; }
    else { h = h_c; bias = bias_c; off = off_c; srcs = srcs_c; out = out_c;
           local = w - nr; sbase = nr; }
    int beg = off[local], end = off[local+1];
    int E = end - beg;
    float adn = ad[sbase + local];
    float a0 = 0.f, a1 = 0.f, a2 = 0.f, a3 = 0.f;
    float inv;
    if (E <= 128) {
        float m = -3.4e38f;
        for (int base = 0; base < E; base += 32) {
            int i = base + lane;
            float e = -3.4e38f;
            if (i < E) {
                int s = srcs[beg + i];
                ssi[wl][i] = s;
                e = as[sbase + s] + adn;
                e = (e > 0.f) ? e : 0.2f*e;
                swg[wl][i] = e;
            }
            m = fmaxf(m, e);
        }
        #pragma unroll
        for (int o = 16; o; o >>= 1) m = fmaxf(m, __shfl_xor_sync(0xffffffffu, m, o));
        float dsum = 0.f;
        for (int base = 0; base < E; base += 32) {
            int i = base + lane;
            if (i < E) {
                float wv = __expf(swg[wl][i] - m);
                swg[wl][i] = wv;
                dsum += wv;
            }
        }
        #pragma unroll
        for (int o = 16; o; o >>= 1) dsum += __shfl_xor_sync(0xffffffffu, dsum, o);
        inv = 1.f / dsum;
        __syncwarp();
        #pragma unroll 4
        for (int e = 0; e < E; e++) {
            int s = ssi[wl][e];
            float al = swg[wl][e];
            const float* hs = h + (size_t)s*HD + lane;
            a0 += al * hs[0];
            a1 += al * hs[32];
            a2 += al * hs[64];
            a3 += al * hs[96];
        }
    } else {
        float m = -3.4e38f;
        for (int i = beg + lane; i < end; i += 32) {
            float e = as[sbase + srcs[i]] + adn;
            e = (e > 0.f) ? e : 0.2f*e;
            m = fmaxf(m, e);
        }
        #pragma unroll
        for (int o = 16; o; o >>= 1) m = fmaxf(m, __shfl_xor_sync(0xffffffffu, m, o));
        float denom = 0.f;
        for (int i = beg; i < end; i++) {
            int s = srcs[i];
            float e = as[sbase + s] + adn;
            e = (e > 0.f) ? e : 0.2f*e;
            float wgt = __expf(e - m);
            denom += wgt;
            const float* hs = h + (size_t)s*HD + lane;
            a0 += wgt * hs[0];
            a1 += wgt * hs[32];
            a2 += wgt * hs[64];
            a3 += wgt * hs[96];
        }
        inv = 1.f / denom;
    }
    float v0 = fmaxf(a0*inv + bias[lane],      0.f);
    float v1 = fmaxf(a1*inv + bias[lane+32],   0.f);
    float v2 = fmaxf(a2*inv + bias[lane+64],   0.f);
    float v3 = fmaxf(a3*inv + bias[lane+96],   0.f);
    float* op = out + (size_t)local*HD + lane;
    op[0] = v0; op[32] = v1; op[64] = v2; op[96] = v3;
    if (epi) {
        __nv_bfloat16* hb = (w < nr) ? hrb : hcb;
        __nv_bfloat16* bp = hb + (size_t)local*HD + lane;
        bp[0]  = __float2bfloat16(v0);
        bp[32] = __float2bfloat16(v1);
        bp[64] = __float2bfloat16(v2);
        bp[96] = __float2bfloat16(v3);
        if (w < nr) {
            float sq = v0*v0 + v1*v1 + v2*v2 + v3*v3;
            #pragma unroll
            for (int o = 16; o; o >>= 1) sq += __shfl_xor_sync(0xffffffffu, sq, o);
            if (lane == 0) rn[local] = sq;
        }
    }
}

// ---------------- bf16 HMMA kNN candidate pass (cp.async pipelined) --------
// 512 threads / 16 warps; warp = (m-tile, n-quarter); NSPLIT=3 -> 120 CTAs.
// Epilogue merges the 4 lane sub-buckets of each (row, quarter) bucket via
// shuffles -> top-3 per (row, quarter, split). NCAND = 3*4*3 = 36.
#define TPAD 136                         // bf16 elements per smem row (272 B)
#define SMB_A   0
#define SMB_B0  (128*TPAD*2)             // 34816
#define SMB_B1  (SMB_B0 + 128*TPAD*2)    // 69632
#define SMB_RN0 (SMB_B1 + 128*TPAD*2)    // 104448
#define SMB_RN1 (SMB_RN0 + 512)          // 104960
#define KNN_SMEM_BYTES (SMB_RN1 + 512)   // 105472
#define KNN_THREADS 512

__device__ __forceinline__ void knn_prefetch(uint32_t sB, uint32_t sRN,
        const __nv_bfloat16* __restrict__ hr, const float* __restrict__ rn,
        int rb, int r_end, int t) {
    #pragma unroll
    for (int i = 0; i < 4; i++) {
        int idx = t + i*KNN_THREADS;
        int row = idx >> 4, seg = idx & 15;
        uint32_t dst = sB + row*(TPAD*2) + seg*16;
        const char* src = (const char*)(hr + (size_t)(rb+row)*HD) + seg*16;
        cp16(dst, src, rb + row < r_end);
    }
    if (t < 32) {
        uint32_t dst = sRN + t*16;
        const char* src = (const char*)(rn + rb) + t*16;
        cp16(dst, src, rb + t*4 < r_end);
    }
}

__global__ void __launch_bounds__(KNN_THREADS, 1) k_knn_mma(
        const __nv_bfloat16* __restrict__ hc,
        const __nv_bfloat16* __restrict__ hr,
        const float* __restrict__ rn,
        int* __restrict__ cand, int nc, int nr) {
    extern __shared__ __align__(16) char dsm[];
    uint32_t sbase = smem_u32(dsm);
    uint32_t sA = sbase + SMB_A;
    __nv_bfloat16* sAp = (__nv_bfloat16*)(dsm + SMB_A);

    int t = threadIdx.x;
    int wid = t >> 5, lane = t & 31;
    int m0 = (wid & 3) * 32;             // warp's collider rows
    int nq = wid >> 2;                   // warp's 32-col resting quarter (0-3)
    int n0 = nq * 32;
    int cb = blockIdx.x * 128;
    int slen = (((nr + NSPLIT - 1) / NSPLIT) + 127) & ~127;
    int r_beg = blockIdx.y * slen;
    int r_end = r_beg + slen; if (r_end > nr) r_end = nr;
    int nchunks = (r_end > r_beg) ? ((r_end - r_beg + 127) >> 7) : 0;

    if (nchunks > 0) {
        knn_prefetch(sbase + SMB_B0, sbase + SMB_RN0, hr, rn, r_beg, r_end, t);
        CP_COMMIT();
    }

    const uint32_t* hc2 = (const uint32_t*)hc;
    for (int idx = t; idx < 128*64; idx += KNN_THREADS) {
        int row = idx >> 6, cp = idx & 63;
        int c = cb + row;
        uint32_t v = (c < nc) ? hc2[(size_t)c*64 + cp] : 0u;
        *(uint32_t*)(sAp + row*TPAD + cp*2) = v;
    }

    const float FINF = __int_as_float(0x7f800000);
    float bd[4][3]; int bi[4][3];
    #pragma unroll
    for (int b = 0; b < 4; b++)
        #pragma unroll
        for (int q = 0; q < 3; q++) { bd[b][q] = FINF; bi[b][q] = 0x7fffffff; }

    for (int ci = 0; ci < nchunks; ci++) {
        int rb = r_beg + ci*128;
        int buf = ci & 1;
        CP_WAIT0();
        __syncthreads();
        if (ci + 1 < nchunks) {
            uint32_t nb_ = buf ? SMB_B0 : SMB_B1;
            uint32_t nrr = buf ? SMB_RN0 : SMB_RN1;
            knn_prefetch(sbase + nb_, sbase + nrr, hr, rn, rb + 128, r_end, t);
            CP_COMMIT();
        }
        uint32_t sB = sbase + (buf ? SMB_B1 : SMB_B0);
        const float* srnp = (const float*)(dsm + (buf ? SMB_RN1 : SMB_RN0));

        float acc[2][4][4];
        #pragma unroll
        for (int mt = 0; mt < 2; mt++)
            #pragma unroll
            for (int nt = 0; nt < 4; nt++)
                #pragma unroll
                for (int q = 0; q < 4; q++) acc[mt][nt][q] = 0.f;

        #pragma unroll
        for (int kk = 0; kk < 8; kk++) {
            int k0 = kk * 16;
            uint32_t afr[2][4];
            #pragma unroll
            for (int mt = 0; mt < 2; mt++) {
                uint32_t addr = sA + ((m0 + mt*16 + (lane & 15))*TPAD
                                      + k0 + (lane >> 4)*8) * 2;
                ldm4(afr[mt], addr);
            }
            #pragma unroll
            for (int nt4 = 0; nt4 < 2; nt4++) {
                uint32_t bfr[4];
                uint32_t addr = sB + ((n0 + nt4*16 + (lane & 7) + ((lane >> 4) & 1)*8)*TPAD
                                      + k0 + ((lane >> 3) & 1)*8) * 2;
                ldm4(bfr, addr);
                #pragma unroll
                for (int mt = 0; mt < 2; mt++) {
                    mma16816(acc[mt][2*nt4],   afr[mt], bfr);
                    mma16816(acc[mt][2*nt4+1], afr[mt], bfr + 2);
                }
            }
        }

        bool full = (rb + 128 <= r_end);
        if (full) {
            #pragma unroll
            for (int mt = 0; mt < 2; mt++) {
                #pragma unroll
                for (int half = 0; half < 2; half++) {
                    int b = mt*2 + half;
                    #pragma unroll
                    for (int nt = 0; nt < 4; nt++) {
                        #pragma unroll
                        for (int q = 0; q < 2; q++) {
                            int col = n0 + nt*8 + (lane & 3)*2 + q;
                            float s = srnp[col] - 2.f * acc[mt][nt][half*2 + q];
                            if (s < bd[b][2]) {
                                bd[b][2] = s; bi[b][2] = rb + col;
                                #pragma unroll
                                for (int z = 2; z > 0; z--) {
                                    if (bd[b][z] < bd[b][z-1]) {
                                        float tf = bd[b][z]; bd[b][z] = bd[b][z-1]; bd[b][z-1] = tf;
                                        int   ti = bi[b][z]; bi[b][z] = bi[b][z-1]; bi[b][z-1] = ti;
                                    }
                                }
                            }
                        }
                    }
                }
            }
        } else {
            #pragma unroll
            for (int mt = 0; mt < 2; mt++) {
                #pragma unroll
                for (int half = 0; half < 2; half++) {
                    int b = mt*2 + half;
                    #pragma unroll
                    for (int nt = 0; nt < 4; nt++) {
                        #pragma unroll
                        for (int q = 0; q < 2; q++) {
                            int col = n0 + nt*8 + (lane & 3)*2 + q;
                            int rcol = rb + col;
                            float s = srnp[col] - 2.f * acc[mt][nt][half*2 + q];
                            if (rcol < r_end && s < bd[b][2]) {
                                bd[b][2] = s; bi[b][2] = rcol;
                                #pragma unroll
                                for (int z = 2; z > 0; z--) {
                                    if (bd[b][z] < bd[b][z-1]) {
                                        float tf = bd[b][z]; bd[b][z] = bd[b][z-1]; bd[b][z-1] = tf;
                                        int   ti = bi[b][z]; bi[b][z] = bi[b][z-1]; bi[b][z-1] = ti;
                                    }
                                }
                            }
                        }
                    }
                }
            }
        }
        __syncthreads();
    }

    // merge 4 lane sub-buckets of each (row, quarter) bucket -> lane&3 == 0
    #pragma unroll
    for (int b = 0; b < 4; b++) {
        #pragma unroll
        for (int j = 1; j < 4; j++) {
            #pragma unroll
            for (int q = 0; q < 3; q++) {
                float od = __shfl_sync(0xffffffffu, bd[b][q], (lane & ~3) + j);
                int   oi = __shfl_sync(0xffffffffu, bi[b][q], (lane & ~3) + j);
                if ((lane & 3) == 0 && od < bd[b][2]) {
                    bd[b][2] = od; bi[b][2] = oi;
                    #pragma unroll
                    for (int z = 2; z > 0; z--) {
                        if (bd[b][z] < bd[b][z-1]) {
                            float tf = bd[b][z]; bd[b][z] = bd[b][z-1]; bd[b][z-1] = tf;
                            int   ti = bi[b][z]; bi[b][z] = bi[b][z-1]; bi[b][z-1] = ti;
                        }
                    }
                }
            }
        }
        if ((lane & 3) == 0) {
            int row = m0 + (b >> 1)*16 + (b & 1)*8 + (lane >> 2);
            int c = cb + row;
            if (c < nc) {
                int* cp = cand + (size_t)c*NCAND + blockIdx.y*12 + nq*3;
                cp[0] = bi[b][0];
                cp[1] = bi[b][1];
                cp[2] = bi[b][2];
            }
        }
    }
}

// exact fp32 rescore -> top-3, fused scatter-mean pool
__global__ void k_rescore_pool(const float* __restrict__ hc, const float* __restrict__ hr,
                               const float* __restrict__ rn, const int* __restrict__ cand,
                               float* psum, float* pcnt, int nc, int nr) {
    int w = (blockIdx.x*blockDim.x + threadIdx.x) >> 5;
    int lane = threadIdx.x & 31;
    if (w >= nc) return;
    const float4* cq = (const float4*)(hc + (size_t)w*HD);
    float4 q = cq[lane];
    float t0 = 3.4e38f, t1 = 3.4e38f, t2 = 3.4e38f;
    int   i0 = 0x7fffffff, i1 = 0x7fffffff, i2 = 0x7fffffff;
    const int* cp = cand + (size_t)w * NCAND;
    for (int qi = 0; qi < NCAND; qi++) {
        int i = cp[qi];
        if ((unsigned)i >= (unsigned)nr) continue;
        const float4 r4 = ((const float4*)(hr + (size_t)i*HD))[lane];
        float dot = q.x*r4.x + q.y*r4.y + q.z*r4.z + q.w*r4.w;
        #pragma unroll
        for (int o = 16; o; o >>= 1) dot += __shfl_xor_sync(0xffffffffu, dot, o);
        float dv = rn[i] - 2.f * dot;
        if (i == i0 || i == i1 || i == i2) continue;
        if (dv < t2 || (dv == t2 && i < i2)) {
            if (dv < t0 || (dv == t0 && i < i0)) {
                t2=t1; i2=i1; t1=t0; i1=i0; t0=dv; i0=i;
            } else if (dv < t1 || (dv == t1 && i < i1)) {
                t2=t1; i2=i1; t1=dv; i1=i;
            } else {
                t2=dv; i2=i;
            }
        }
    }
    int nb[3] = { i0, i1, i2 };
    #pragma unroll
    for (int z = 0; z < 3; z++) {
        int r = nb[z];
        if ((unsigned)r >= (unsigned)nr) continue;   // sentinel safety
        float* pp = psum + (size_t)r*HD + lane*4;
        atomicAdd(pp + 0, q.x);
        atomicAdd(pp + 1, q.y);
        atomicAdd(pp + 2, q.z);
        atomicAdd(pp + 3, q.w);
        if (lane == 0) atomicAdd(&pcnt[r], 1.f);
    }
}

__global__ void k_decode(const float* __restrict__ hr, const float* __restrict__ psum,
                         const float* __restrict__ pcnt,
                         const float* __restrict__ Wd, const float* __restrict__ bd,
                         float* __restrict__ out, int n) {
    int w = (blockIdx.x*blockDim.x + threadIdx.x) >> 5;
    int lane = threadIdx.x & 31;
    if (w >= n) return;
    float inv = 1.f / fmaxf(pcnt[w], 1.f);
    float a0 = 0.f, a1 = 0.f, a2 = 0.f;
    #pragma unroll
    for (int i = 0; i < 4; i++) {
        int j = lane + 32*i;
        float v = hr[(size_t)w*HD + j];
        float p = psum[(size_t)w*HD + j] * inv;
        a0 += v*Wd[j*3 + 0] + p*Wd[(HD + j)*3 + 0];
        a1 += v*Wd[j*3 + 1] + p*Wd[(HD + j)*3 + 1];
        a2 += v*Wd[j*3 + 2] + p*Wd[(HD + j)*3 + 2];
    }
    #pragma unroll
    for (int o = 16; o; o >>= 1) {
        a0 += __shfl_xor_sync(0xffffffffu, a0, o);
        a1 += __shfl_xor_sync(0xffffffffu, a1, o);
        a2 += __shfl_xor_sync(0xffffffffu, a2, o);
    }
    if (lane == 0) {
        out[w*3 + 0] = a0 + bd[0];
        out[w*3 + 1] = a1 + bd[1];
        out[w*3 + 2] = a2 + bd[2];
    }
}

// ---------------- host ----------------
static inline int cdiv(int a, int b) { return (a + b - 1) / b; }

extern "C" void kernel_launch(void* const* d_in, const int* in_sizes, int n_in,
                              void* d_out, int out_size) {
    const float* x_r  = (const float*)d_in[0];
    const int*   ei_r = (const int*)  d_in[1];
    const float* x_c  = (const float*)d_in[2];
    const int*   ei_c = (const int*)  d_in[3];
    const float* W1r  = (const float*)d_in[4];
    const float* as1r = (const float*)d_in[5];
    const float* ad1r = (const float*)d_in[6];
    const float* b1r  = (const float*)d_in[7];
    const float* W2r  = (const float*)d_in[8];
    const float* as2r = (const float*)d_in[9];
    const float* ad2r = (const float*)d_in[10];
    const float* b2r  = (const float*)d_in[11];
    const float* W1c  = (const float*)d_in[12];
    const float* as1c = (const float*)d_in[13];
    const float* ad1c = (const float*)d_in[14];
    const float* b1c  = (const float*)d_in[15];
    const float* W2c  = (const float*)d_in[16];
    const float* as2c = (const float*)d_in[17];
    const float* ad2c = (const float*)d_in[18];
    const float* b2c  = (const float*)d_in[19];
    const float* Wd   = (const float*)d_in[20];
    const float* bd   = (const float*)d_in[21];
    float* out = (float*)d_out;

    int nr = in_sizes[0] / 3;
    int er = in_sizes[1] / 2;
    int nc = in_sizes[2] / 6;
    int ec = in_sizes[3] / 2;

    float *hA_r, *hB_r, *hA_c, *hB_c, *as_p, *ad_p, *rn, *psum, *pcnt;
    __nv_bfloat16 *hrb, *hcb;
    int *cnt_r, *off_r, *cur_r, *srcs_r, *cnt_c, *off_c, *cur_c, *srcs_c, *cand;
    cudaGetSymbolAddress((void**)&hA_r,  d_hA_r);
    cudaGetSymbolAddress((void**)&hB_r,  d_hB_r);
    cudaGetSymbolAddress((void**)&hA_c,  d_hA_c);
    cudaGetSymbolAddress((void**)&hB_c,  d_hB_c);
    cudaGetSymbolAddress((void**)&hrb,   d_hrb);
    cudaGetSymbolAddress((void**)&hcb,   d_hcb);
    cudaGetSymbolAddress((void**)&as_p,  d_as);
    cudaGetSymbolAddress((void**)&ad_p,  d_ad);
    cudaGetSymbolAddress((void**)&cnt_r, d_cnt_r);
    cudaGetSymbolAddress((void**)&off_r, d_off_r);
    cudaGetSymbolAddress((void**)&cur_r, d_cur_r);
    cudaGetSymbolAddress((void**)&srcs_r,d_srcs_r);
    cudaGetSymbolAddress((void**)&cnt_c, d_cnt_c);
    cudaGetSymbolAddress((void**)&off_c, d_off_c);
    cudaGetSymbolAddress((void**)&cur_c, d_cur_c);
    cudaGetSymbolAddress((void**)&srcs_c,d_srcs_c);
    cudaGetSymbolAddress((void**)&rn,    d_rn);
    cudaGetSymbolAddress((void**)&cand,  d_cand);
    cudaGetSymbolAddress((void**)&psum,  d_psum);
    cudaGetSymbolAddress((void**)&pcnt,  d_pcnt);

    cudaFuncSetAttribute(k_knn_mma, cudaFuncAttributeMaxDynamicSharedMemorySize,
                         KNN_SMEM_BYTES);

    // 1. fills
    k_init<<<cdiv(nr*HD,256),256>>>(cnt_r, cnt_c, psum, pcnt, nr, nc);
    // 2-3. CSR histogram + scan
    k_hist_both<<<cdiv(er+ec,256),256>>>(ei_r, er, cnt_r, ei_c, ec, cnt_c);
    k_scan_both<<<2,1024>>>(cnt_r, off_r, cur_r, nr, cnt_c, off_c, cur_c, nc);
    // 4. CSR scatter (clock canary in ncu slot)
    k_scatter_both<<<cdiv(er+nr+ec+nc,256),256>>>(ei_r, er, nr, cur_r, srcs_r,
                                                  ei_c, ec, nc, cur_c, srcs_c);
    // 5. layer-1 linear + scores (both)
    k_lin_small_both<<<nr+nc,128>>>(x_r, W1r, as1r, ad1r, x_c, W1c, as1c, ad1c,
                                    hA_r, hA_c, as_p, ad_p, nr, nc);
    // 6. layer-1 aggregate (both)
    k_agg_both<<<cdiv((nr+nc)*32,128),128>>>(hA_r, hA_c, as_p, ad_p,
                                             off_r, srcs_r, off_c, srcs_c,
                                             b1r, b1c, hB_r, hB_c,
                                             (__nv_bfloat16*)0, (__nv_bfloat16*)0,
                                             (float*)0, nr, nc, 0);
    // 7. layer-2 linear + scores (both)
    {
        int nb_r = cdiv(nr,16);
        int nb_c = cdiv(nc,16);
        k_lin128_both<<<nb_r+nb_c,128>>>(hB_r, W2r, as2r, ad2r, hB_c, W2c, as2c, ad2c,
                                         hA_r, hA_c, as_p, ad_p, nr, nc, nb_r);
    }
    // 8. layer-2 aggregate + bf16 convert + rnorm (both)
    k_agg_both<<<cdiv((nr+nc)*32,128),128>>>(hA_r, hA_c, as_p, ad_p,
                                             off_r, srcs_r, off_c, srcs_c,
                                             b2r, b2c, hB_r, hB_c,
                                             hrb, hcb, rn, nr, nc, 1);
    // 9. kNN candidates (bf16 HMMA, 512 threads, warp-merged buckets)
    {
        dim3 g(cdiv(nc,128), NSPLIT);
        k_knn_mma<<<g, KNN_THREADS, KNN_SMEM_BYTES>>>(hcb, hrb, rn, cand, nc, nr);
    }
    // 10. exact rescore (36 candidates) + pool
    k_rescore_pool<<<cdiv(nc*32,256),256>>>(hB_c, hB_r, rn, cand, psum, pcnt, nc, nr);
    // 11. decode
    k_decode<<<cdiv(nr*32,256),256>>>(hB_r, psum, pcnt, Wd, bd, out, nr);
}